// round 14
// baseline (speedup 1.0000x reference)
#include <cuda_runtime.h>
#include <cuda_fp16.h>
#include <cstdint>

#define NUM_E 8
#define TOK   16384
#define DIN   2048
#define DOUT  2048
#define RNK   64
#define LSCALE 2.0f

// ---------------------------------------------------------------------------
// Scratch (allocation-free device globals) — fp16, rna-rounded
// ---------------------------------------------------------------------------
__device__ __half xh_g[(size_t)TOK * DIN];                 // x
__device__ __half wah_g[(size_t)NUM_E * DIN * RNK];        // w_a  [E][K][R]
__device__ __half wbh_g[(size_t)NUM_E * RNK * DOUT];       // w_b  [E][R][N]
__device__ __half weff_g[(size_t)NUM_E * DIN * DOUT];      // w_base + SCALE*w_a@w_b

__device__ __forceinline__ int find_expert(const int* __restrict__ tpe, int m0) {
    int e = 0, cum = 0;
#pragma unroll
    for (int i = 0; i < NUM_E; ++i) {
        cum += tpe[i];
        if (m0 >= cum) e++;
    }
    return e;
}

__device__ __forceinline__ uint32_t smem_u32(const void* p) {
    uint32_t a;
    asm("{ .reg .u64 t; cvta.to.shared.u64 t, %1; cvt.u32.u64 %0, t; }"
        : "=r"(a) : "l"(p));
    return a;
}

__device__ __forceinline__ void cp16(uint32_t dst, const void* src) {
    asm volatile("cp.async.cg.shared.global [%0], [%1], 16;" :: "r"(dst), "l"(src));
}
#define CP_COMMIT() asm volatile("cp.async.commit_group;" ::: "memory")
#define CP_WAIT(n)  asm volatile("cp.async.wait_group %0;" :: "n"(n) : "memory")

__device__ __forceinline__ void ldsm4(unsigned& r0, unsigned& r1, unsigned& r2,
                                      unsigned& r3, uint32_t addr) {
    asm volatile("ldmatrix.sync.aligned.m8n8.x4.shared.b16 {%0,%1,%2,%3}, [%4];"
                 : "=r"(r0), "=r"(r1), "=r"(r2), "=r"(r3) : "r"(addr));
}
__device__ __forceinline__ void ldsm4t(unsigned& r0, unsigned& r1, unsigned& r2,
                                       unsigned& r3, uint32_t addr) {
    asm volatile("ldmatrix.sync.aligned.m8n8.x4.trans.shared.b16 {%0,%1,%2,%3}, [%4];"
                 : "=r"(r0), "=r"(r1), "=r"(r2), "=r"(r3) : "r"(addr));
}

__device__ __forceinline__ void mma16(float* c,
                                      unsigned a0, unsigned a1, unsigned a2, unsigned a3,
                                      unsigned b0, unsigned b1) {
    asm volatile(
        "mma.sync.aligned.m16n8k16.row.col.f32.f16.f16.f32 "
        "{%0,%1,%2,%3}, {%4,%5,%6,%7}, {%8,%9}, {%0,%1,%2,%3};"
        : "+f"(c[0]), "+f"(c[1]), "+f"(c[2]), "+f"(c[3])
        : "r"(a0), "r"(a1), "r"(a2), "r"(a3), "r"(b0), "r"(b1));
}

// ---------------------------------------------------------------------------
// Kernel 0: straight fp32 -> fp16 (rna) conversion, 8 elems/thread
// ---------------------------------------------------------------------------
__global__ void __launch_bounds__(256)
conv_half_kernel(const float* __restrict__ src, __half* __restrict__ dst) {
    size_t i = ((size_t)blockIdx.x * 256 + threadIdx.x) * 8;
    float4 v0 = *(const float4*)(src + i);
    float4 v1 = *(const float4*)(src + i + 4);
    __half2 h[4];
    h[0] = __floats2half2_rn(v0.x, v0.y);
    h[1] = __floats2half2_rn(v0.z, v0.w);
    h[2] = __floats2half2_rn(v1.x, v1.y);
    h[3] = __floats2half2_rn(v1.z, v1.w);
    *(uint4*)(dst + i) = *(uint4*)h;
}

// ---------------------------------------------------------------------------
// Kernel 1: W_eff[e] = fp16( w_base[e] + LSCALE * (w_a[e] @ w_b[e]) )
// 64x64 tiles, 128 threads, warp grid 2m x 2n, warp tile 32x32. 5 CTAs/SM.
// (R12 config — best measured)
// ---------------------------------------------------------------------------
#define W_AST 72     // 64+8
#define W_BST 72     // 64+8
#define W_AH  (64 * W_AST)            // 4608 halves
#define W_BH  (64 * W_BST)            // 4608 halves
#define W_AB_BYTES ((W_AH + W_BH) * 2)  // 18432 B
#define W_STST 68    // fp32 staging stride (floats)
#define W_OST  72    // fp16 output staging stride (halves) — reuses A/B region
#define W_SMEM (W_AB_BYTES + 64 * W_STST * 4)   // 35840 B

__global__ void __launch_bounds__(128, 5)
weff_kernel(const float* __restrict__ w_base)
{
    extern __shared__ __align__(16) char smraw[];
    const uint32_t sbase = smem_u32(smraw);
    const uint32_t bbase = sbase + W_AH * 2u;
    const uint32_t stbase = sbase + W_AB_BYTES;
    float* stage = (float*)(smraw + W_AB_BYTES);
    __half* ostage = (__half*)smraw;          // reuses A region after MMA

    const int tid = threadIdx.x;
    const int m0 = blockIdx.x * 64;
    const int n0 = blockIdx.y * 64;
    const int e = blockIdx.z;
    const __half* wa = wah_g + (size_t)e * DIN * RNK + (size_t)m0 * RNK;
    const __half* wbl = wbh_g + (size_t)e * RNK * DOUT + n0;
    const float* wbsrc = w_base + (size_t)e * DIN * DOUT + (size_t)m0 * DOUT + n0;
    __half* weff = weff_g + (size_t)e * DIN * DOUT + (size_t)m0 * DOUT + n0;

    const int warp = tid >> 5, lane = tid & 31;
    const int wm = warp >> 1, wn = warp & 1;
    const int g = lane >> 2, t = lane & 3;

    const int arow = ((lane >> 3) & 1) * 8 + (lane & 7);
    const int akoff = (lane >> 4) * 8;
    const int bm = lane >> 3;
    const int bkrow = (bm & 1) * 8 + (lane & 7);
    const int bnoff = (bm >> 1) * 8;

#pragma unroll
    for (int i = 0; i < 4; ++i) {
        int idx = tid + i * 128;
        int row = idx >> 3, q = (idx & 7) * 8;
        cp16(sbase + (uint32_t)(row * W_AST + q) * 2u, wa + (size_t)row * RNK + q);
    }
#pragma unroll
    for (int i = 0; i < 4; ++i) {
        int idx = tid + i * 128;
        int row = idx >> 3, q = (idx & 7) * 8;
        cp16(bbase + (uint32_t)(row * W_BST + q) * 2u, wbl + (size_t)row * DOUT + q);
    }
    CP_COMMIT();

#pragma unroll
    for (int i = 0; i < 8; ++i) {
        int idx = tid + i * 128;
        int row = idx >> 4, q = (idx & 15) * 4;
        cp16(stbase + (uint32_t)(row * W_STST + q) * 4u, wbsrc + (size_t)row * DOUT + q);
    }
    CP_COMMIT();

    CP_WAIT(1);
    __syncthreads();

    float acc[2][4][4];
#pragma unroll
    for (int i = 0; i < 2; i++)
#pragma unroll
        for (int j = 0; j < 4; j++)
#pragma unroll
            for (int k = 0; k < 4; k++) acc[i][j][k] = 0.f;

    const uint32_t ao = sbase + (uint32_t)((wm * 32 + arow) * W_AST + akoff) * 2u;
    const uint32_t bo = bbase + (uint32_t)(bkrow * W_BST + wn * 32 + bnoff) * 2u;
#pragma unroll
    for (int ks = 0; ks < 4; ++ks) {
        const int kk = ks * 16;
        unsigned af[2][4], bf[4][2];
#pragma unroll
        for (int mt = 0; mt < 2; ++mt)
            ldsm4(af[mt][0], af[mt][1], af[mt][2], af[mt][3],
                  ao + (uint32_t)(mt * 16 * W_AST + kk) * 2u);
#pragma unroll
        for (int p = 0; p < 2; ++p)
            ldsm4t(bf[2 * p][0], bf[2 * p][1], bf[2 * p + 1][0], bf[2 * p + 1][1],
                   bo + (uint32_t)(kk * W_BST + p * 16) * 2u);
#pragma unroll
        for (int mt = 0; mt < 2; ++mt)
#pragma unroll
            for (int nt = 0; nt < 4; ++nt)
                mma16(acc[mt][nt], af[mt][0], af[mt][1], af[mt][2], af[mt][3],
                      bf[nt][0], bf[nt][1]);
    }

    CP_WAIT(0);
    __syncthreads();

#pragma unroll
    for (int mt = 0; mt < 2; ++mt)
#pragma unroll
        for (int nt = 0; nt < 4; ++nt) {
            int rl = wm * 32 + mt * 16 + g;
            int cl = wn * 32 + nt * 8 + 2 * t;
            float2 b0 = *(const float2*)&stage[rl * W_STST + cl];
            float2 b1 = *(const float2*)&stage[(rl + 8) * W_STST + cl];
            __half2 v0 = __floats2half2_rn(b0.x + LSCALE * acc[mt][nt][0],
                                           b0.y + LSCALE * acc[mt][nt][1]);
            __half2 v1 = __floats2half2_rn(b1.x + LSCALE * acc[mt][nt][2],
                                           b1.y + LSCALE * acc[mt][nt][3]);
            *(__half2*)&ostage[rl * W_OST + cl] = v0;
            *(__half2*)&ostage[(rl + 8) * W_OST + cl] = v1;
        }
    __syncthreads();

#pragma unroll
    for (int i = 0; i < 4; ++i) {
        int u = tid + i * 128;
        int row = u >> 3, c8 = (u & 7) * 8;
        uint4 v = *(uint4*)&ostage[row * W_OST + c8];
        *(uint4*)&weff[(size_t)row * DOUT + c8] = v;
    }
}

// ---------------------------------------------------------------------------
// Kernel 2: main GEMM. out = xh @ W_eff[e]   (K = 2048)
// BM=128 BN=256 BK=32; 256 threads, 8 warps (2m x 4n), warp tile 64x64;
// ldmatrix + trans; 4-stage cp.async; fp32 accumulators; 1 CTA/SM.
// Rationale: BN=256 amortizes A-tile loads over 2x output -> 25% fewer
// LDGSTS per SM-kt; 256-reg/thread cap (1 CTA) avoids accumulator spills.
// ---------------------------------------------------------------------------
#define BN   256
#define AST  40
#define BST  264                        // 256+8 (132 words ≡ 4 mod 32: ldsm-safe)
#define A_H  (128 * AST)                // 5120 halves
#define B_H  (32 * BST)                 // 8448 halves
#define STAGE_H (A_H + B_H)             // 13568 halves
#define NKT  (DIN / 32)                 // 64
#define GEMM_SMEM (4 * STAGE_H * 2)     // 108544 B

__global__ void __launch_bounds__(256, 1)
gemm_main(const int* __restrict__ tpe, float* __restrict__ out)
{
    extern __shared__ __align__(16) __half sm[];
    const uint32_t sbase = smem_u32(sm);

    const int tid = threadIdx.x;
    const int m0 = blockIdx.x * 128;   // m fastest: wave shares weight slice via L2
    const int n0 = blockIdx.y * BN;
    const int e = find_expert(tpe, m0);
    const __half* wb = weff_g + (size_t)e * DIN * DOUT + n0;
    const __half* xa = xh_g + (size_t)m0 * DIN;

    const int warp = tid >> 5, lane = tid & 31;
    const int wm = warp >> 2, wn = warp & 3;
    const int g = lane >> 2, t = lane & 3;

    const int arow = ((lane >> 3) & 1) * 8 + (lane & 7);
    const int akoff = (lane >> 4) * 8;
    const int bm = lane >> 3;
    const int bkrow = (bm & 1) * 8 + (lane & 7);
    const int bnoff = (bm >> 1) * 8;

    auto load_stage = [&](int kt, int s) {
        const int k0 = kt * 32;
        const uint32_t abase = sbase + (uint32_t)(s * STAGE_H) * 2u;
        const uint32_t bbase = abase + A_H * 2u;
        // A tile: 128 x 32 halves = 512 cp16 -> 2 iters of 256 threads
#pragma unroll
        for (int i = 0; i < 2; ++i) {
            int idx = tid + i * 256;
            int row = idx >> 2, q = (idx & 3) * 8;
            cp16(abase + (uint32_t)(row * AST + q) * 2u,
                 xa + (size_t)row * DIN + k0 + q);
        }
        // B tile: 32 x 256 halves = 1024 cp16 -> 4 iters
#pragma unroll
        for (int i = 0; i < 4; ++i) {
            int idx = tid + i * 256;
            int row = idx >> 5, q = (idx & 31) * 8;
            cp16(bbase + (uint32_t)(row * BST + q) * 2u,
                 wb + (size_t)(k0 + row) * DOUT + q);
        }
    };

    float acc[4][8][4];
#pragma unroll
    for (int i = 0; i < 4; i++)
#pragma unroll
        for (int j = 0; j < 8; j++)
#pragma unroll
            for (int k = 0; k < 4; k++) acc[i][j][k] = 0.f;

#pragma unroll
    for (int p = 0; p < 3; ++p) { load_stage(p, p); CP_COMMIT(); }

#pragma unroll 1
    for (int kt = 0; kt < NKT; ++kt) {
        CP_WAIT(2);
        __syncthreads();
        const int kp = kt + 3;
        if (kp < NKT) load_stage(kp, kp & 3);
        CP_COMMIT();

        const uint32_t Ab = sbase + (uint32_t)((kt & 3) * STAGE_H) * 2u;
        const uint32_t Bb = Ab + A_H * 2u;
        const uint32_t aoff = Ab + (uint32_t)((wm * 64 + arow) * AST + akoff) * 2u;
        const uint32_t boff = Bb + (uint32_t)(bkrow * BST + wn * 64 + bnoff) * 2u;
#pragma unroll
        for (int ks = 0; ks < 2; ++ks) {
            const int kk = ks * 16;
            unsigned af[4][4], bf[8][2];
#pragma unroll
            for (int mt = 0; mt < 4; ++mt)
                ldsm4(af[mt][0], af[mt][1], af[mt][2], af[mt][3],
                      aoff + (uint32_t)(mt * 16 * AST + kk) * 2u);
#pragma unroll
            for (int p = 0; p < 4; ++p)
                ldsm4t(bf[2 * p][0], bf[2 * p][1], bf[2 * p + 1][0], bf[2 * p + 1][1],
                       boff + (uint32_t)(kk * BST + p * 16) * 2u);
#pragma unroll
            for (int mt = 0; mt < 4; ++mt)
#pragma unroll
                for (int nt = 0; nt < 8; ++nt)
                    mma16(acc[mt][nt], af[mt][0], af[mt][1], af[mt][2], af[mt][3],
                          bf[nt][0], bf[nt][1]);
        }
    }

#pragma unroll
    for (int mt = 0; mt < 4; ++mt)
#pragma unroll
        for (int nt = 0; nt < 8; ++nt) {
            int r = m0 + wm * 64 + mt * 16 + g;
            int c = n0 + wn * 64 + nt * 8 + 2 * t;
            float2 v0 = {acc[mt][nt][0], acc[mt][nt][1]};
            float2 v1 = {acc[mt][nt][2], acc[mt][nt][3]};
            *(float2*)&out[(size_t)r * DOUT + c] = v0;
            *(float2*)&out[(size_t)(r + 8) * DOUT + c] = v1;
        }
}

// ---------------------------------------------------------------------------
extern "C" void kernel_launch(void* const* d_in, const int* in_sizes, int n_in,
                              void* d_out, int out_size) {
    const float* x      = (const float*)d_in[0];
    const int*   tpe    = (const int*)d_in[1];
    const float* w_base = (const float*)d_in[2];
    const float* w_a    = (const float*)d_in[3];
    const float* w_b    = (const float*)d_in[4];
    float* out = (float*)d_out;
    (void)in_sizes; (void)n_in; (void)out_size;

    __half* xh = nullptr;  cudaGetSymbolAddress((void**)&xh,  xh_g);
    __half* wah = nullptr; cudaGetSymbolAddress((void**)&wah, wah_g);
    __half* wbh = nullptr; cudaGetSymbolAddress((void**)&wbh, wbh_g);

    // 0) fp32 -> fp16 conversions (x, w_a, w_b only; w_base consumed fp32)
    conv_half_kernel<<<(TOK * DIN) / 2048, 256>>>(x, xh);
    conv_half_kernel<<<((size_t)NUM_E * DIN * RNK) / 2048, 256>>>(w_a, wah);
    conv_half_kernel<<<((size_t)NUM_E * RNK * DOUT) / 2048, 256>>>(w_b, wbh);

    // 1) W_eff = w_base + SCALE * w_a @ w_b  (R12 config)
    cudaFuncSetAttribute(weff_kernel, cudaFuncAttributeMaxDynamicSharedMemorySize, W_SMEM);
    weff_kernel<<<dim3(DIN / 64, DOUT / 64, NUM_E), 128, W_SMEM>>>(w_base);

    // 2) main GEMM: out = xh @ W_eff[e]  (K = 2048, BN = 256)
    cudaFuncSetAttribute(gemm_main, cudaFuncAttributeMaxDynamicSharedMemorySize, GEMM_SMEM);
    gemm_main<<<dim3(TOK / 128, DOUT / BN), 256, GEMM_SMEM>>>(tpe, out);
}

// round 15
// speedup vs baseline: 1.3735x; 1.3735x over previous
#include <cuda_runtime.h>
#include <cuda_fp16.h>
#include <cstdint>

#define NUM_E 8
#define TOK   16384
#define DIN   2048
#define DOUT  2048
#define RNK   64
#define LSCALE 2.0f

// ---------------------------------------------------------------------------
// Scratch (allocation-free device globals) — fp16, rna-rounded
// ---------------------------------------------------------------------------
__device__ __half xh_g[(size_t)TOK * DIN];                 // x
__device__ __half wah_g[(size_t)NUM_E * DIN * RNK];        // w_a  [E][K][R]
__device__ __half wbh_g[(size_t)NUM_E * RNK * DOUT];       // w_b  [E][R][N]
__device__ __half weff_g[(size_t)NUM_E * DIN * DOUT];      // w_base + SCALE*w_a@w_b

__device__ __forceinline__ int find_expert(const int* __restrict__ tpe, int m0) {
    int e = 0, cum = 0;
#pragma unroll
    for (int i = 0; i < NUM_E; ++i) {
        cum += tpe[i];
        if (m0 >= cum) e++;
    }
    return e;
}

__device__ __forceinline__ uint32_t smem_u32(const void* p) {
    uint32_t a;
    asm("{ .reg .u64 t; cvta.to.shared.u64 t, %1; cvt.u32.u64 %0, t; }"
        : "=r"(a) : "l"(p));
    return a;
}

__device__ __forceinline__ void cp16(uint32_t dst, const void* src) {
    asm volatile("cp.async.cg.shared.global [%0], [%1], 16;" :: "r"(dst), "l"(src));
}
#define CP_COMMIT() asm volatile("cp.async.commit_group;" ::: "memory")
#define CP_WAIT(n)  asm volatile("cp.async.wait_group %0;" :: "n"(n) : "memory")

__device__ __forceinline__ void ldsm4(unsigned& r0, unsigned& r1, unsigned& r2,
                                      unsigned& r3, uint32_t addr) {
    asm volatile("ldmatrix.sync.aligned.m8n8.x4.shared.b16 {%0,%1,%2,%3}, [%4];"
                 : "=r"(r0), "=r"(r1), "=r"(r2), "=r"(r3) : "r"(addr));
}
__device__ __forceinline__ void ldsm4t(unsigned& r0, unsigned& r1, unsigned& r2,
                                       unsigned& r3, uint32_t addr) {
    asm volatile("ldmatrix.sync.aligned.m8n8.x4.trans.shared.b16 {%0,%1,%2,%3}, [%4];"
                 : "=r"(r0), "=r"(r1), "=r"(r2), "=r"(r3) : "r"(addr));
}

__device__ __forceinline__ void mma16(float* c,
                                      unsigned a0, unsigned a1, unsigned a2, unsigned a3,
                                      unsigned b0, unsigned b1) {
    asm volatile(
        "mma.sync.aligned.m16n8k16.row.col.f32.f16.f16.f32 "
        "{%0,%1,%2,%3}, {%4,%5,%6,%7}, {%8,%9}, {%0,%1,%2,%3};"
        : "+f"(c[0]), "+f"(c[1]), "+f"(c[2]), "+f"(c[3])
        : "r"(a0), "r"(a1), "r"(a2), "r"(a3), "r"(b0), "r"(b1));
}

// ---------------------------------------------------------------------------
// Kernel 0: straight fp32 -> fp16 (rna) conversion, 8 elems/thread
// ---------------------------------------------------------------------------
__global__ void __launch_bounds__(256)
conv_half_kernel(const float* __restrict__ src, __half* __restrict__ dst) {
    size_t i = ((size_t)blockIdx.x * 256 + threadIdx.x) * 8;
    float4 v0 = *(const float4*)(src + i);
    float4 v1 = *(const float4*)(src + i + 4);
    __half2 h[4];
    h[0] = __floats2half2_rn(v0.x, v0.y);
    h[1] = __floats2half2_rn(v0.z, v0.w);
    h[2] = __floats2half2_rn(v1.x, v1.y);
    h[3] = __floats2half2_rn(v1.z, v1.w);
    *(uint4*)(dst + i) = *(uint4*)h;
}

// ---------------------------------------------------------------------------
// Kernel 1: W_eff[e] = fp16( w_base[e] + LSCALE * (w_a[e] @ w_b[e]) )
// 64x64 tiles, 128 threads, warp grid 2m x 2n, warp tile 32x32. 5 CTAs/SM.
// (R12 config — best measured)
// ---------------------------------------------------------------------------
#define W_AST 72     // 64+8
#define W_BST 72     // 64+8
#define W_AH  (64 * W_AST)            // 4608 halves
#define W_BH  (64 * W_BST)            // 4608 halves
#define W_AB_BYTES ((W_AH + W_BH) * 2)  // 18432 B
#define W_STST 68    // fp32 staging stride (floats)
#define W_OST  72    // fp16 output staging stride (halves) — reuses A/B region
#define W_SMEM (W_AB_BYTES + 64 * W_STST * 4)   // 35840 B

__global__ void __launch_bounds__(128, 5)
weff_kernel(const float* __restrict__ w_base)
{
    extern __shared__ __align__(16) char smraw[];
    const uint32_t sbase = smem_u32(smraw);
    const uint32_t bbase = sbase + W_AH * 2u;
    const uint32_t stbase = sbase + W_AB_BYTES;
    float* stage = (float*)(smraw + W_AB_BYTES);
    __half* ostage = (__half*)smraw;          // reuses A region after MMA

    const int tid = threadIdx.x;
    const int m0 = blockIdx.x * 64;
    const int n0 = blockIdx.y * 64;
    const int e = blockIdx.z;
    const __half* wa = wah_g + (size_t)e * DIN * RNK + (size_t)m0 * RNK;
    const __half* wbl = wbh_g + (size_t)e * RNK * DOUT + n0;
    const float* wbsrc = w_base + (size_t)e * DIN * DOUT + (size_t)m0 * DOUT + n0;
    __half* weff = weff_g + (size_t)e * DIN * DOUT + (size_t)m0 * DOUT + n0;

    const int warp = tid >> 5, lane = tid & 31;
    const int wm = warp >> 1, wn = warp & 1;
    const int g = lane >> 2, t = lane & 3;

    const int arow = ((lane >> 3) & 1) * 8 + (lane & 7);
    const int akoff = (lane >> 4) * 8;
    const int bm = lane >> 3;
    const int bkrow = (bm & 1) * 8 + (lane & 7);
    const int bnoff = (bm >> 1) * 8;

#pragma unroll
    for (int i = 0; i < 4; ++i) {
        int idx = tid + i * 128;
        int row = idx >> 3, q = (idx & 7) * 8;
        cp16(sbase + (uint32_t)(row * W_AST + q) * 2u, wa + (size_t)row * RNK + q);
    }
#pragma unroll
    for (int i = 0; i < 4; ++i) {
        int idx = tid + i * 128;
        int row = idx >> 3, q = (idx & 7) * 8;
        cp16(bbase + (uint32_t)(row * W_BST + q) * 2u, wbl + (size_t)row * DOUT + q);
    }
    CP_COMMIT();

#pragma unroll
    for (int i = 0; i < 8; ++i) {
        int idx = tid + i * 128;
        int row = idx >> 4, q = (idx & 15) * 4;
        cp16(stbase + (uint32_t)(row * W_STST + q) * 4u, wbsrc + (size_t)row * DOUT + q);
    }
    CP_COMMIT();

    CP_WAIT(1);
    __syncthreads();

    float acc[2][4][4];
#pragma unroll
    for (int i = 0; i < 2; i++)
#pragma unroll
        for (int j = 0; j < 4; j++)
#pragma unroll
            for (int k = 0; k < 4; k++) acc[i][j][k] = 0.f;

    const uint32_t ao = sbase + (uint32_t)((wm * 32 + arow) * W_AST + akoff) * 2u;
    const uint32_t bo = bbase + (uint32_t)(bkrow * W_BST + wn * 32 + bnoff) * 2u;
#pragma unroll
    for (int ks = 0; ks < 4; ++ks) {
        const int kk = ks * 16;
        unsigned af[2][4], bf[4][2];
#pragma unroll
        for (int mt = 0; mt < 2; ++mt)
            ldsm4(af[mt][0], af[mt][1], af[mt][2], af[mt][3],
                  ao + (uint32_t)(mt * 16 * W_AST + kk) * 2u);
#pragma unroll
        for (int p = 0; p < 2; ++p)
            ldsm4t(bf[2 * p][0], bf[2 * p][1], bf[2 * p + 1][0], bf[2 * p + 1][1],
                   bo + (uint32_t)(kk * W_BST + p * 16) * 2u);
#pragma unroll
        for (int mt = 0; mt < 2; ++mt)
#pragma unroll
            for (int nt = 0; nt < 4; ++nt)
                mma16(acc[mt][nt], af[mt][0], af[mt][1], af[mt][2], af[mt][3],
                      bf[nt][0], bf[nt][1]);
    }

    CP_WAIT(0);
    __syncthreads();

#pragma unroll
    for (int mt = 0; mt < 2; ++mt)
#pragma unroll
        for (int nt = 0; nt < 4; ++nt) {
            int rl = wm * 32 + mt * 16 + g;
            int cl = wn * 32 + nt * 8 + 2 * t;
            float2 b0 = *(const float2*)&stage[rl * W_STST + cl];
            float2 b1 = *(const float2*)&stage[(rl + 8) * W_STST + cl];
            __half2 v0 = __floats2half2_rn(b0.x + LSCALE * acc[mt][nt][0],
                                           b0.y + LSCALE * acc[mt][nt][1]);
            __half2 v1 = __floats2half2_rn(b1.x + LSCALE * acc[mt][nt][2],
                                           b1.y + LSCALE * acc[mt][nt][3]);
            *(__half2*)&ostage[rl * W_OST + cl] = v0;
            *(__half2*)&ostage[(rl + 8) * W_OST + cl] = v1;
        }
    __syncthreads();

#pragma unroll
    for (int i = 0; i < 4; ++i) {
        int u = tid + i * 128;
        int row = u >> 3, c8 = (u & 7) * 8;
        uint4 v = *(uint4*)&ostage[row * W_OST + c8];
        *(uint4*)&weff[(size_t)row * DOUT + c8] = v;
    }
}

// ---------------------------------------------------------------------------
// Kernel 2: main GEMM. out = xh @ W_eff[e]   (K = 2048)
// BM=128 BN=128 BK=32; 4 warps (2x2), warp tile 64x64; ldmatrix + trans;
// 4-stage cp.async; fp32 accumulators; 2 CTAs/SM.  (R12 config)
// Grid ordering: n FASTEST — each ~296-CTA wave covers 16 n-blocks x ~18
// m-blocks, shrinking the wave working set (x slice + ~1 expert's weights)
// to ~20 MB (L2-resident) instead of re-streaming all of x every wave.
// ---------------------------------------------------------------------------
#define AST 40
#define BST 136
#define A_H (128 * AST)                 // 5120 halves
#define B_H (32 * BST)                  // 4352 halves
#define STAGE_H (A_H + B_H)             // 9472 halves
#define NKT (DIN / 32)                  // 64
#define GEMM_SMEM (4 * STAGE_H * 2)     // 75776 B

__global__ void __launch_bounds__(128, 2)
gemm_main(const int* __restrict__ tpe, float* __restrict__ out)
{
    extern __shared__ __align__(16) __half sm[];
    const uint32_t sbase = smem_u32(sm);

    const int tid = threadIdx.x;
    const int n0 = blockIdx.x * 128;   // n fastest: wave working set L2-resident
    const int m0 = blockIdx.y * 128;
    const int e = find_expert(tpe, m0);
    const __half* wb = weff_g + (size_t)e * DIN * DOUT + n0;
    const __half* xa = xh_g + (size_t)m0 * DIN;

    const int warp = tid >> 5, lane = tid & 31;
    const int wm = warp >> 1, wn = warp & 1;
    const int g = lane >> 2, t = lane & 3;

    const int arow = ((lane >> 3) & 1) * 8 + (lane & 7);
    const int akoff = (lane >> 4) * 8;
    const int bm = lane >> 3;
    const int bkrow = (bm & 1) * 8 + (lane & 7);
    const int bnoff = (bm >> 1) * 8;

    auto load_stage = [&](int kt, int s) {
        const int k0 = kt * 32;
        const uint32_t abase = sbase + (uint32_t)(s * STAGE_H) * 2u;
        const uint32_t bbase = abase + A_H * 2u;
#pragma unroll
        for (int i = 0; i < 4; ++i) {
            int idx = tid + i * 128;
            int row = idx >> 2, q = (idx & 3) * 8;
            cp16(abase + (uint32_t)(row * AST + q) * 2u,
                 xa + (size_t)row * DIN + k0 + q);
        }
#pragma unroll
        for (int i = 0; i < 4; ++i) {
            int idx = tid + i * 128;
            int row = idx >> 4, q = (idx & 15) * 8;
            cp16(bbase + (uint32_t)(row * BST + q) * 2u,
                 wb + (size_t)(k0 + row) * DOUT + q);
        }
    };

    float acc[4][8][4];
#pragma unroll
    for (int i = 0; i < 4; i++)
#pragma unroll
        for (int j = 0; j < 8; j++)
#pragma unroll
            for (int k = 0; k < 4; k++) acc[i][j][k] = 0.f;

#pragma unroll
    for (int p = 0; p < 3; ++p) { load_stage(p, p); CP_COMMIT(); }

#pragma unroll 1
    for (int kt = 0; kt < NKT; ++kt) {
        CP_WAIT(2);
        __syncthreads();
        const int kp = kt + 3;
        if (kp < NKT) load_stage(kp, kp & 3);
        CP_COMMIT();

        const uint32_t Ab = sbase + (uint32_t)((kt & 3) * STAGE_H) * 2u;
        const uint32_t Bb = Ab + A_H * 2u;
        const uint32_t aoff = Ab + (uint32_t)((wm * 64 + arow) * AST + akoff) * 2u;
        const uint32_t boff = Bb + (uint32_t)(bkrow * BST + wn * 64 + bnoff) * 2u;
#pragma unroll
        for (int ks = 0; ks < 2; ++ks) {
            const int kk = ks * 16;
            unsigned af[4][4], bf[8][2];
#pragma unroll
            for (int mt = 0; mt < 4; ++mt)
                ldsm4(af[mt][0], af[mt][1], af[mt][2], af[mt][3],
                      aoff + (uint32_t)(mt * 16 * AST + kk) * 2u);
#pragma unroll
            for (int p = 0; p < 4; ++p)
                ldsm4t(bf[2 * p][0], bf[2 * p][1], bf[2 * p + 1][0], bf[2 * p + 1][1],
                       boff + (uint32_t)(kk * BST + p * 16) * 2u);
#pragma unroll
            for (int mt = 0; mt < 4; ++mt)
#pragma unroll
                for (int nt = 0; nt < 8; ++nt)
                    mma16(acc[mt][nt], af[mt][0], af[mt][1], af[mt][2], af[mt][3],
                          bf[nt][0], bf[nt][1]);
        }
    }

#pragma unroll
    for (int mt = 0; mt < 4; ++mt)
#pragma unroll
        for (int nt = 0; nt < 8; ++nt) {
            int r = m0 + wm * 64 + mt * 16 + g;
            int c = n0 + wn * 64 + nt * 8 + 2 * t;
            float2 v0 = {acc[mt][nt][0], acc[mt][nt][1]};
            float2 v1 = {acc[mt][nt][2], acc[mt][nt][3]};
            *(float2*)&out[(size_t)r * DOUT + c] = v0;
            *(float2*)&out[(size_t)(r + 8) * DOUT + c] = v1;
        }
}

// ---------------------------------------------------------------------------
extern "C" void kernel_launch(void* const* d_in, const int* in_sizes, int n_in,
                              void* d_out, int out_size) {
    const float* x      = (const float*)d_in[0];
    const int*   tpe    = (const int*)d_in[1];
    const float* w_base = (const float*)d_in[2];
    const float* w_a    = (const float*)d_in[3];
    const float* w_b    = (const float*)d_in[4];
    float* out = (float*)d_out;
    (void)in_sizes; (void)n_in; (void)out_size;

    __half* xh = nullptr;  cudaGetSymbolAddress((void**)&xh,  xh_g);
    __half* wah = nullptr; cudaGetSymbolAddress((void**)&wah, wah_g);
    __half* wbh = nullptr; cudaGetSymbolAddress((void**)&wbh, wbh_g);

    // 0) fp32 -> fp16 conversions (x, w_a, w_b only; w_base consumed fp32)
    conv_half_kernel<<<(TOK * DIN) / 2048, 256>>>(x, xh);
    conv_half_kernel<<<((size_t)NUM_E * DIN * RNK) / 2048, 256>>>(w_a, wah);
    conv_half_kernel<<<((size_t)NUM_E * RNK * DOUT) / 2048, 256>>>(w_b, wbh);

    // 1) W_eff = w_base + SCALE * w_a @ w_b  (R12 config)
    cudaFuncSetAttribute(weff_kernel, cudaFuncAttributeMaxDynamicSharedMemorySize, W_SMEM);
    weff_kernel<<<dim3(DIN / 64, DOUT / 64, NUM_E), 128, W_SMEM>>>(w_base);

    // 2) main GEMM: out = xh @ W_eff[e]  (K = 2048, n-fastest grid)
    cudaFuncSetAttribute(gemm_main, cudaFuncAttributeMaxDynamicSharedMemorySize, GEMM_SMEM);
    gemm_main<<<dim3(DOUT / 128, TOK / 128), 128, GEMM_SMEM>>>(tpe, out);
}

// round 16
// speedup vs baseline: 1.3937x; 1.0147x over previous
#include <cuda_runtime.h>
#include <cuda_fp16.h>
#include <cstdint>

#define NUM_E 8
#define TOK   16384
#define DIN   2048
#define DOUT  2048
#define RNK   64
#define LSCALE 2.0f

// ---------------------------------------------------------------------------
// Scratch (allocation-free device globals) — fp16, rna-rounded
// ---------------------------------------------------------------------------
__device__ __half xh_g[(size_t)TOK * DIN];                 // x
__device__ __half wah_g[(size_t)NUM_E * DIN * RNK];        // w_a  [E][K][R]
__device__ __half wbh_g[(size_t)NUM_E * RNK * DOUT];       // w_b  [E][R][N]
__device__ __half weff_g[(size_t)NUM_E * DIN * DOUT];      // w_base + SCALE*w_a@w_b

#define X_ELEMS   ((size_t)TOK * DIN)            // 33554432
#define WA_ELEMS  ((size_t)NUM_E * DIN * RNK)    // 1048576
#define WB_ELEMS  ((size_t)NUM_E * RNK * DOUT)   // 1048576

__device__ __forceinline__ int find_expert(const int* __restrict__ tpe, int m0) {
    int e = 0, cum = 0;
#pragma unroll
    for (int i = 0; i < NUM_E; ++i) {
        cum += tpe[i];
        if (m0 >= cum) e++;
    }
    return e;
}

__device__ __forceinline__ uint32_t smem_u32(const void* p) {
    uint32_t a;
    asm("{ .reg .u64 t; cvta.to.shared.u64 t, %1; cvt.u32.u64 %0, t; }"
        : "=r"(a) : "l"(p));
    return a;
}

__device__ __forceinline__ void cp16(uint32_t dst, const void* src) {
    asm volatile("cp.async.cg.shared.global [%0], [%1], 16;" :: "r"(dst), "l"(src));
}
#define CP_COMMIT() asm volatile("cp.async.commit_group;" ::: "memory")
#define CP_WAIT(n)  asm volatile("cp.async.wait_group %0;" :: "n"(n) : "memory")

__device__ __forceinline__ void ldsm4(unsigned& r0, unsigned& r1, unsigned& r2,
                                      unsigned& r3, uint32_t addr) {
    asm volatile("ldmatrix.sync.aligned.m8n8.x4.shared.b16 {%0,%1,%2,%3}, [%4];"
                 : "=r"(r0), "=r"(r1), "=r"(r2), "=r"(r3) : "r"(addr));
}
__device__ __forceinline__ void ldsm4t(unsigned& r0, unsigned& r1, unsigned& r2,
                                       unsigned& r3, uint32_t addr) {
    asm volatile("ldmatrix.sync.aligned.m8n8.x4.trans.shared.b16 {%0,%1,%2,%3}, [%4];"
                 : "=r"(r0), "=r"(r1), "=r"(r2), "=r"(r3) : "r"(addr));
}

__device__ __forceinline__ void mma16(float* c,
                                      unsigned a0, unsigned a1, unsigned a2, unsigned a3,
                                      unsigned b0, unsigned b1) {
    asm volatile(
        "mma.sync.aligned.m16n8k16.row.col.f32.f16.f16.f32 "
        "{%0,%1,%2,%3}, {%4,%5,%6,%7}, {%8,%9}, {%0,%1,%2,%3};"
        : "+f"(c[0]), "+f"(c[1]), "+f"(c[2]), "+f"(c[3])
        : "r"(a0), "r"(a1), "r"(a2), "r"(a3), "r"(b0), "r"(b1));
}

// ---------------------------------------------------------------------------
// Kernel 0: fused fp32 -> fp16 (rna) conversion of x, w_a, w_b in ONE launch.
// Segment boundaries are 2048-aligned, so each 256-thread block (2048 elems)
// maps to exactly one segment.
// ---------------------------------------------------------------------------
__global__ void __launch_bounds__(256)
conv_all_kernel(const float* __restrict__ x, const float* __restrict__ w_a,
                const float* __restrict__ w_b) {
    size_t i = ((size_t)blockIdx.x * 256 + threadIdx.x) * 8;
    const float* src;
    __half* dst;
    if (i < X_ELEMS)                    { src = x + i;                dst = xh_g + i; }
    else if (i < X_ELEMS + WA_ELEMS)    { size_t j = i - X_ELEMS;     src = w_a + j; dst = wah_g + j; }
    else                                { size_t j = i - X_ELEMS - WA_ELEMS; src = w_b + j; dst = wbh_g + j; }
    float4 v0 = *(const float4*)(src);
    float4 v1 = *(const float4*)(src + 4);
    __half2 h[4];
    h[0] = __floats2half2_rn(v0.x, v0.y);
    h[1] = __floats2half2_rn(v0.z, v0.w);
    h[2] = __floats2half2_rn(v1.x, v1.y);
    h[3] = __floats2half2_rn(v1.z, v1.w);
    *(uint4*)(dst) = *(uint4*)h;
}

// ---------------------------------------------------------------------------
// Kernel 1: W_eff[e] = fp16( w_base[e] + LSCALE * (w_a[e] @ w_b[e]) )
// 64x64 tiles, 128 threads, warp grid 2m x 2n, warp tile 32x32. 5 CTAs/SM.
// (R12 config — best measured)
// ---------------------------------------------------------------------------
#define W_AST 72     // 64+8
#define W_BST 72     // 64+8
#define W_AH  (64 * W_AST)            // 4608 halves
#define W_BH  (64 * W_BST)            // 4608 halves
#define W_AB_BYTES ((W_AH + W_BH) * 2)  // 18432 B
#define W_STST 68    // fp32 staging stride (floats)
#define W_OST  72    // fp16 output staging stride (halves) — reuses A/B region
#define W_SMEM (W_AB_BYTES + 64 * W_STST * 4)   // 35840 B

__global__ void __launch_bounds__(128, 5)
weff_kernel(const float* __restrict__ w_base)
{
    extern __shared__ __align__(16) char smraw[];
    const uint32_t sbase = smem_u32(smraw);
    const uint32_t bbase = sbase + W_AH * 2u;
    const uint32_t stbase = sbase + W_AB_BYTES;
    float* stage = (float*)(smraw + W_AB_BYTES);
    __half* ostage = (__half*)smraw;          // reuses A region after MMA

    const int tid = threadIdx.x;
    const int m0 = blockIdx.x * 64;
    const int n0 = blockIdx.y * 64;
    const int e = blockIdx.z;
    const __half* wa = wah_g + (size_t)e * DIN * RNK + (size_t)m0 * RNK;
    const __half* wbl = wbh_g + (size_t)e * RNK * DOUT + n0;
    const float* wbsrc = w_base + (size_t)e * DIN * DOUT + (size_t)m0 * DOUT + n0;
    __half* weff = weff_g + (size_t)e * DIN * DOUT + (size_t)m0 * DOUT + n0;

    const int warp = tid >> 5, lane = tid & 31;
    const int wm = warp >> 1, wn = warp & 1;
    const int g = lane >> 2, t = lane & 3;

    const int arow = ((lane >> 3) & 1) * 8 + (lane & 7);
    const int akoff = (lane >> 4) * 8;
    const int bm = lane >> 3;
    const int bkrow = (bm & 1) * 8 + (lane & 7);
    const int bnoff = (bm >> 1) * 8;

#pragma unroll
    for (int i = 0; i < 4; ++i) {
        int idx = tid + i * 128;
        int row = idx >> 3, q = (idx & 7) * 8;
        cp16(sbase + (uint32_t)(row * W_AST + q) * 2u, wa + (size_t)row * RNK + q);
    }
#pragma unroll
    for (int i = 0; i < 4; ++i) {
        int idx = tid + i * 128;
        int row = idx >> 3, q = (idx & 7) * 8;
        cp16(bbase + (uint32_t)(row * W_BST + q) * 2u, wbl + (size_t)row * DOUT + q);
    }
    CP_COMMIT();

#pragma unroll
    for (int i = 0; i < 8; ++i) {
        int idx = tid + i * 128;
        int row = idx >> 4, q = (idx & 15) * 4;
        cp16(stbase + (uint32_t)(row * W_STST + q) * 4u, wbsrc + (size_t)row * DOUT + q);
    }
    CP_COMMIT();

    CP_WAIT(1);
    __syncthreads();

    float acc[2][4][4];
#pragma unroll
    for (int i = 0; i < 2; i++)
#pragma unroll
        for (int j = 0; j < 4; j++)
#pragma unroll
            for (int k = 0; k < 4; k++) acc[i][j][k] = 0.f;

    const uint32_t ao = sbase + (uint32_t)((wm * 32 + arow) * W_AST + akoff) * 2u;
    const uint32_t bo = bbase + (uint32_t)(bkrow * W_BST + wn * 32 + bnoff) * 2u;
#pragma unroll
    for (int ks = 0; ks < 4; ++ks) {
        const int kk = ks * 16;
        unsigned af[2][4], bf[4][2];
#pragma unroll
        for (int mt = 0; mt < 2; ++mt)
            ldsm4(af[mt][0], af[mt][1], af[mt][2], af[mt][3],
                  ao + (uint32_t)(mt * 16 * W_AST + kk) * 2u);
#pragma unroll
        for (int p = 0; p < 2; ++p)
            ldsm4t(bf[2 * p][0], bf[2 * p][1], bf[2 * p + 1][0], bf[2 * p + 1][1],
                   bo + (uint32_t)(kk * W_BST + p * 16) * 2u);
#pragma unroll
        for (int mt = 0; mt < 2; ++mt)
#pragma unroll
            for (int nt = 0; nt < 4; ++nt)
                mma16(acc[mt][nt], af[mt][0], af[mt][1], af[mt][2], af[mt][3],
                      bf[nt][0], bf[nt][1]);
    }

    CP_WAIT(0);
    __syncthreads();

#pragma unroll
    for (int mt = 0; mt < 2; ++mt)
#pragma unroll
        for (int nt = 0; nt < 4; ++nt) {
            int rl = wm * 32 + mt * 16 + g;
            int cl = wn * 32 + nt * 8 + 2 * t;
            float2 b0 = *(const float2*)&stage[rl * W_STST + cl];
            float2 b1 = *(const float2*)&stage[(rl + 8) * W_STST + cl];
            __half2 v0 = __floats2half2_rn(b0.x + LSCALE * acc[mt][nt][0],
                                           b0.y + LSCALE * acc[mt][nt][1]);
            __half2 v1 = __floats2half2_rn(b1.x + LSCALE * acc[mt][nt][2],
                                           b1.y + LSCALE * acc[mt][nt][3]);
            *(__half2*)&ostage[rl * W_OST + cl] = v0;
            *(__half2*)&ostage[(rl + 8) * W_OST + cl] = v1;
        }
    __syncthreads();

#pragma unroll
    for (int i = 0; i < 4; ++i) {
        int u = tid + i * 128;
        int row = u >> 3, c8 = (u & 7) * 8;
        uint4 v = *(uint4*)&ostage[row * W_OST + c8];
        *(uint4*)&weff[(size_t)row * DOUT + c8] = v;
    }
}

// ---------------------------------------------------------------------------
// Kernel 2: main GEMM. out = xh @ W_eff[e]   (K = 2048)
// BM=128 BN=128 BK=32; 4 warps (2x2), warp tile 64x64; ldmatrix + trans;
// 4-stage cp.async; fp32 accumulators; 2 CTAs/SM.  (best measured config)
// ---------------------------------------------------------------------------
#define AST 40
#define BST 136
#define A_H (128 * AST)                 // 5120 halves
#define B_H (32 * BST)                  // 4352 halves
#define STAGE_H (A_H + B_H)             // 9472 halves
#define NKT (DIN / 32)                  // 64
#define GEMM_SMEM (4 * STAGE_H * 2)     // 75776 B

__global__ void __launch_bounds__(128, 2)
gemm_main(const int* __restrict__ tpe, float* __restrict__ out)
{
    extern __shared__ __align__(16) __half sm[];
    const uint32_t sbase = smem_u32(sm);

    const int tid = threadIdx.x;
    const int n0 = blockIdx.x * 128;   // n fastest: wave working set L2-resident
    const int m0 = blockIdx.y * 128;
    const int e = find_expert(tpe, m0);
    const __half* wb = weff_g + (size_t)e * DIN * DOUT + n0;
    const __half* xa = xh_g + (size_t)m0 * DIN;

    const int warp = tid >> 5, lane = tid & 31;
    const int wm = warp >> 1, wn = warp & 1;
    const int g = lane >> 2, t = lane & 3;

    const int arow = ((lane >> 3) & 1) * 8 + (lane & 7);
    const int akoff = (lane >> 4) * 8;
    const int bm = lane >> 3;
    const int bkrow = (bm & 1) * 8 + (lane & 7);
    const int bnoff = (bm >> 1) * 8;

    auto load_stage = [&](int kt, int s) {
        const int k0 = kt * 32;
        const uint32_t abase = sbase + (uint32_t)(s * STAGE_H) * 2u;
        const uint32_t bbase = abase + A_H * 2u;
#pragma unroll
        for (int i = 0; i < 4; ++i) {
            int idx = tid + i * 128;
            int row = idx >> 2, q = (idx & 3) * 8;
            cp16(abase + (uint32_t)(row * AST + q) * 2u,
                 xa + (size_t)row * DIN + k0 + q);
        }
#pragma unroll
        for (int i = 0; i < 4; ++i) {
            int idx = tid + i * 128;
            int row = idx >> 4, q = (idx & 15) * 8;
            cp16(bbase + (uint32_t)(row * BST + q) * 2u,
                 wb + (size_t)(k0 + row) * DOUT + q);
        }
    };

    float acc[4][8][4];
#pragma unroll
    for (int i = 0; i < 4; i++)
#pragma unroll
        for (int j = 0; j < 8; j++)
#pragma unroll
            for (int k = 0; k < 4; k++) acc[i][j][k] = 0.f;

#pragma unroll
    for (int p = 0; p < 3; ++p) { load_stage(p, p); CP_COMMIT(); }

#pragma unroll 1
    for (int kt = 0; kt < NKT; ++kt) {
        CP_WAIT(2);
        __syncthreads();
        const int kp = kt + 3;
        if (kp < NKT) load_stage(kp, kp & 3);
        CP_COMMIT();

        const uint32_t Ab = sbase + (uint32_t)((kt & 3) * STAGE_H) * 2u;
        const uint32_t Bb = Ab + A_H * 2u;
        const uint32_t aoff = Ab + (uint32_t)((wm * 64 + arow) * AST + akoff) * 2u;
        const uint32_t boff = Bb + (uint32_t)(bkrow * BST + wn * 64 + bnoff) * 2u;
#pragma unroll
        for (int ks = 0; ks < 2; ++ks) {
            const int kk = ks * 16;
            unsigned af[4][4], bf[8][2];
#pragma unroll
            for (int mt = 0; mt < 4; ++mt)
                ldsm4(af[mt][0], af[mt][1], af[mt][2], af[mt][3],
                      aoff + (uint32_t)(mt * 16 * AST + kk) * 2u);
#pragma unroll
            for (int p = 0; p < 4; ++p)
                ldsm4t(bf[2 * p][0], bf[2 * p][1], bf[2 * p + 1][0], bf[2 * p + 1][1],
                       boff + (uint32_t)(kk * BST + p * 16) * 2u);
#pragma unroll
            for (int mt = 0; mt < 4; ++mt)
#pragma unroll
                for (int nt = 0; nt < 8; ++nt)
                    mma16(acc[mt][nt], af[mt][0], af[mt][1], af[mt][2], af[mt][3],
                          bf[nt][0], bf[nt][1]);
        }
    }

#pragma unroll
    for (int mt = 0; mt < 4; ++mt)
#pragma unroll
        for (int nt = 0; nt < 8; ++nt) {
            int r = m0 + wm * 64 + mt * 16 + g;
            int c = n0 + wn * 64 + nt * 8 + 2 * t;
            float2 v0 = {acc[mt][nt][0], acc[mt][nt][1]};
            float2 v1 = {acc[mt][nt][2], acc[mt][nt][3]};
            *(float2*)&out[(size_t)r * DOUT + c] = v0;
            *(float2*)&out[(size_t)(r + 8) * DOUT + c] = v1;
        }
}

// ---------------------------------------------------------------------------
extern "C" void kernel_launch(void* const* d_in, const int* in_sizes, int n_in,
                              void* d_out, int out_size) {
    const float* x      = (const float*)d_in[0];
    const int*   tpe    = (const int*)d_in[1];
    const float* w_base = (const float*)d_in[2];
    const float* w_a    = (const float*)d_in[3];
    const float* w_b    = (const float*)d_in[4];
    float* out = (float*)d_out;
    (void)in_sizes; (void)n_in; (void)out_size;

    // 0) fused fp32 -> fp16 conversions (x, w_a, w_b) in one launch
    const int conv_blocks = (int)((X_ELEMS + WA_ELEMS + WB_ELEMS) / 2048);
    conv_all_kernel<<<conv_blocks, 256>>>(x, w_a, w_b);

    // 1) W_eff = w_base + SCALE * w_a @ w_b  (R12 config)
    cudaFuncSetAttribute(weff_kernel, cudaFuncAttributeMaxDynamicSharedMemorySize, W_SMEM);
    weff_kernel<<<dim3(DIN / 64, DOUT / 64, NUM_E), 128, W_SMEM>>>(w_base);

    // 2) main GEMM: out = xh @ W_eff[e]  (K = 2048, n-fastest grid)
    cudaFuncSetAttribute(gemm_main, cudaFuncAttributeMaxDynamicSharedMemorySize, GEMM_SMEM);
    gemm_main<<<dim3(DOUT / 128, TOK / 128), 128, GEMM_SMEM>>>(tpe, out);
}